// round 17
// baseline (speedup 1.0000x reference)
#include <cuda_runtime.h>
#include <cuda_fp16.h>
#include <cuda_fp8.h>
#include <math.h>
#include <stdint.h>

// ---------------------------------------------------------------------------
// Problem constants
// ---------------------------------------------------------------------------
static constexpr int NT = 2048;      // tokens (B*L)
static constexpr int NH = 64;
static constexpr int NV = 32000;
static constexpr int K16 = 192;      // fp16 K-range: 64 freq + 64 cos + 64 sin
static constexpr int K8  = 256;      // fp8  K-range: hidden (synthesis)

// GEMM tiling
static constexpr int CTA_M = 128;
static constexpr int CTA_N = 128;
static constexpr int NCHUNK = 5;     // 3 fp16 chunks (KC=64) + 2 fp8 chunks (KC=128)

// SMEM: three rotating 32KB stages (A 16KB + B 16KB), SW128-swizzled 128B rows.
static constexpr int A_BYTES = 16384;
static constexpr int B_BYTES = 16384;
static constexpr int STAGE_BYTES = A_BYTES + B_BYTES;            // 32768
static constexpr int OFF_B  = A_BYTES;
static constexpr int SMEM_TOTAL = 3 * STAGE_BYTES;               // 98304 -> 2 CTAs/SM

// prep_fused block ranges
static constexpr int NB_TOK = NT / 4;                 // 512
static constexpr int NB_VOC = NV * 8 / 256;           // 1000
static constexpr int NB_WVT = (NV / 32) * (256 / 32); // 8000
static constexpr int NB_PREP = NB_TOK + NB_VOC + NB_WVT;

// ---------------------------------------------------------------------------
// Device scratch (allocation-free)
// ---------------------------------------------------------------------------
__device__ __half         g_A16[NT * K16];
__device__ __nv_fp8_e4m3  g_A8 [NT * K8];
__device__ __half         g_B16[(size_t)NV * K16];
__device__ __nv_fp8_e4m3  g_B8 [(size_t)NV * K8];
__device__ float g_v2[NV];     // from QUANTIZED vocab freqs
__device__ float g_f2[NT];     // from QUANTIZED token freqs
__device__ float g_lamp[NT];

// ---------------------------------------------------------------------------
// Helpers
// ---------------------------------------------------------------------------
__device__ __forceinline__ uint32_t smem_u32(const void* p) {
    uint32_t a;
    asm("{ .reg .u64 t; cvta.to.shared.u64 t, %1; cvt.u32.u64 %0, t; }" : "=r"(a) : "l"(p));
    return a;
}

__device__ __forceinline__ void cpa16(uint32_t saddr, const void* gaddr) {
    asm volatile("cp.async.cg.shared.global [%0], [%1], 16;" :: "r"(saddr), "l"(gaddr));
}
#define CPA_COMMIT() asm volatile("cp.async.commit_group;" ::: "memory")
#define CPA_WAIT1()  asm volatile("cp.async.wait_group 1;" ::: "memory")
#define CPA_WAIT0()  asm volatile("cp.async.wait_group 0;" ::: "memory")

#define LDSM_X4(r, addr) \
    asm volatile("ldmatrix.sync.aligned.m8n8.x4.shared.b16 {%0,%1,%2,%3}, [%4];" \
        : "=r"((r)[0]), "=r"((r)[1]), "=r"((r)[2]), "=r"((r)[3]) : "r"(addr))

#define MMA16816(C, A, B0, B1) \
    asm volatile("mma.sync.aligned.m16n8k16.row.col.f32.f16.f16.f32 " \
        "{%0,%1,%2,%3}, {%4,%5,%6,%7}, {%8,%9}, {%0,%1,%2,%3};" \
        : "+f"((C)[0]), "+f"((C)[1]), "+f"((C)[2]), "+f"((C)[3]) \
        : "r"((A)[0]), "r"((A)[1]), "r"((A)[2]), "r"((A)[3]), "r"(B0), "r"(B1))

#define MMA16832F8(C, A, B0, B1) \
    asm volatile("mma.sync.aligned.m16n8k32.row.col.f32.e4m3.e4m3.f32 " \
        "{%0,%1,%2,%3}, {%4,%5,%6,%7}, {%8,%9}, {%0,%1,%2,%3};" \
        : "+f"((C)[0]), "+f"((C)[1]), "+f"((C)[2]), "+f"((C)[3]) \
        : "r"((A)[0]), "r"((A)[1]), "r"((A)[2]), "r"((A)[3]), "r"(B0), "r"(B1))

__device__ __forceinline__ float gelu_exact(float x) {
    return 0.5f * x * (1.0f + erff(x * 0.7071067811865476f));
}

// ---------------------------------------------------------------------------
// Fused prep kernel: one launch, three block-range branches.
//   [0, 512)        token MLP + trig -> g_A16/g_A8, g_f2 (quantized), g_lamp
//   [512, 1512)     vocab features   -> g_B16, g_v2 (quantized)
//   [1512, 9512)    Wv transpose     -> g_B8 (e4m3)
// A16 row [t][192]: [0,64)=freq, [64,128)=cos(ph)*sc, [128,192)=sin(ph)*sc
// A8  row [t][256]: 0.1*x.    sc = (0.5/64)*log1p(sum amps)
// ---------------------------------------------------------------------------
__global__ void __launch_bounds__(256)
prep_fused(const float* __restrict__ wave,
           const float* __restrict__ W0, const float* __restrict__ b0,
           const float* __restrict__ W1, const float* __restrict__ b1,
           const float* __restrict__ W2, const float* __restrict__ b2,
           const float* __restrict__ rw,
           const float* __restrict__ vf, const float* __restrict__ vp,
           const float* __restrict__ Wv)
{
    const int bid = blockIdx.x;

    if (bid < NB_TOK) {
        // ---------------- token prep: 4 tokens / block ----------------
        __shared__ float sw[4][192];
        __shared__ float sx[4][256];
        __shared__ float sy[4][256];
        __shared__ float slamp[4];

        const int t0 = bid * 4;
        const int j  = threadIdx.x;

        for (int i = j; i < 4 * 192; i += 256) {
            int tok = i / 192, kk = i % 192;
            sw[tok][kk] = wave[(size_t)(t0 + tok) * 192 + kk];
        }
        __syncthreads();

        if (j < 8) {
            int tok = j & 3;
            if (j < 4) {
                float s = 0.f;
                for (int h = 0; h < NH; h++) {
                    float q = __half2float(__float2half_rn(sw[tok][h]));
                    s = fmaf(q, q, s);
                }
                g_f2[t0 + tok] = s;
            } else {
                float s = 0.f;
                for (int h = 0; h < NH; h++) s += sw[tok][64 + h];
                float l = log1pf(s);
                slamp[tok] = l;
                g_lamp[t0 + tok] = l;
            }
        }

        float acc0 = 0.f, acc1 = 0.f, acc2 = 0.f, acc3 = 0.f;
        float bb = b0[j];
        for (int k = 0; k < 192; k++) {
            float w = W0[k * 256 + j];
            acc0 = fmaf(sw[0][k], w, acc0);
            acc1 = fmaf(sw[1][k], w, acc1);
            acc2 = fmaf(sw[2][k], w, acc2);
            acc3 = fmaf(sw[3][k], w, acc3);
        }
        __syncthreads();
        sx[0][j] = gelu_exact(acc0 + bb);
        sx[1][j] = gelu_exact(acc1 + bb);
        sx[2][j] = gelu_exact(acc2 + bb);
        sx[3][j] = gelu_exact(acc3 + bb);
        __syncthreads();

        bb = b1[j];
        float r1 = rw[1];
        acc0 = acc1 = acc2 = acc3 = 0.f;
        for (int k = 0; k < 256; k++) {
            float w = W1[k * 256 + j];
            acc0 = fmaf(sx[0][k], w, acc0);
            acc1 = fmaf(sx[1][k], w, acc1);
            acc2 = fmaf(sx[2][k], w, acc2);
            acc3 = fmaf(sx[3][k], w, acc3);
        }
        sy[0][j] = gelu_exact(acc0 + bb) + r1 * sx[0][j];
        sy[1][j] = gelu_exact(acc1 + bb) + r1 * sx[1][j];
        sy[2][j] = gelu_exact(acc2 + bb) + r1 * sx[2][j];
        sy[3][j] = gelu_exact(acc3 + bb) + r1 * sx[3][j];
        __syncthreads();

        bb = b2[j];
        float r2 = rw[2];
        acc0 = acc1 = acc2 = acc3 = 0.f;
        for (int k = 0; k < 256; k++) {
            float w = W2[k * 256 + j];
            acc0 = fmaf(sy[0][k], w, acc0);
            acc1 = fmaf(sy[1][k], w, acc1);
            acc2 = fmaf(sy[2][k], w, acc2);
            acc3 = fmaf(sy[3][k], w, acc3);
        }
        {
            float z[4];
            z[0] = 0.1f * (gelu_exact(acc0 + bb) + r2 * sy[0][j]);
            z[1] = 0.1f * (gelu_exact(acc1 + bb) + r2 * sy[1][j]);
            z[2] = 0.1f * (gelu_exact(acc2 + bb) + r2 * sy[2][j]);
            z[3] = 0.1f * (gelu_exact(acc3 + bb) + r2 * sy[3][j]);
            #pragma unroll
            for (int i = 0; i < 4; i++)
                g_A8[(size_t)(t0 + i) * K8 + j] = __nv_fp8_e4m3(z[i]);
        }
        {
            int i = j >> 6, h = j & 63;
            float f  = sw[i][h];
            float ph = sw[i][128 + h];
            float sc = 0.0078125f * slamp[i];
            float sn, cs;
            sincosf(ph, &sn, &cs);
            size_t base = (size_t)(t0 + i) * K16;
            g_A16[base + h]        = __float2half_rn(f);
            g_A16[base + 64 + h]   = __float2half_rn(cs * sc);
            g_A16[base + 128 + h]  = __float2half_rn(sn * sc);
        }
    } else if (bid < NB_TOK + NB_VOC) {
        // ---------------- vocab features: 8 threads / row ----------------
        int t = (bid - NB_TOK) * 256 + threadIdx.x;
        int v  = t >> 3;
        int hb = (t & 7) * 8;
        const float* fr = vf + (size_t)v * NH + hb;
        const float* pr = vp + (size_t)v * NH + hb;
        float4 fa = *(const float4*)fr;
        float4 fb = *(const float4*)(fr + 4);
        float4 pa = *(const float4*)pr;
        float4 pb = *(const float4*)(pr + 4);
        float f[8] = {fa.x, fa.y, fa.z, fa.w, fb.x, fb.y, fb.z, fb.w};
        float p[8] = {pa.x, pa.y, pa.z, pa.w, pb.x, pb.y, pb.z, pb.w};

        __align__(16) __half hi8[8], cs8[8], sn8[8];
        float s2 = 0.f;
        #pragma unroll
        for (int i = 0; i < 8; i++) {
            __half h = __float2half_rn(f[i]);
            hi8[i] = h;
            float q = __half2float(h);
            s2 = fmaf(q, q, s2);
            float sn, cs;
            sincosf(p[i], &sn, &cs);
            cs8[i] = __float2half_rn(cs);
            sn8[i] = __float2half_rn(sn);
        }
        size_t base = (size_t)v * K16 + hb;
        *(uint4*)(g_B16 + base)        = *(uint4*)hi8;
        *(uint4*)(g_B16 + base + 64)   = *(uint4*)cs8;
        *(uint4*)(g_B16 + base + 128)  = *(uint4*)sn8;

        s2 += __shfl_down_sync(0xffffffffu, s2, 4);
        s2 += __shfl_down_sync(0xffffffffu, s2, 2);
        s2 += __shfl_down_sync(0xffffffffu, s2, 1);
        if ((t & 7) == 0) g_v2[v] = s2;
    } else {
        // ---------------- Wv transpose: 32x32 tile / block, e4m3 out ------
        __shared__ float st[32][33];    // st[v-local][k-local]
        int wb = bid - NB_TOK - NB_VOC;
        const int v0 = (wb / 8) * 32;
        const int k0 = (wb % 8) * 32;
        const int tx = threadIdx.x & 31, ty = threadIdx.x >> 5;
        #pragma unroll
        for (int r = 0; r < 4; r++)
            st[tx][ty + r * 8] = Wv[(size_t)(k0 + ty + r * 8) * NV + v0 + tx];
        __syncthreads();
        int tid = threadIdx.x;
        int vl = tid >> 3, kg = tid & 7;
        __align__(4) __nv_fp8_e4m3 pk[4];
        #pragma unroll
        for (int j = 0; j < 4; j++)
            pk[j] = __nv_fp8_e4m3(st[vl][kg * 4 + j]);
        *(uint32_t*)(g_B8 + (size_t)(v0 + vl) * K8 + k0 + kg * 4) = *(uint32_t*)pk;
    }
}

// ---------------------------------------------------------------------------
// Main GEMM: chunks 0-2 fp16 m16n8k16 (KC=64), chunks 3-4 e4m3 m16n8k32
// (KC=128, same byte addressing — fragment byte layouts are identical).
// CTA 128x128, 8 warps (2M x 4N), warp tile 64x32, 96KB -> 2 CTAs/SM.
// Three rotating 32KB stages, prefetch depth 2, one barrier per chunk.
// After chunk 0 (cross term): acc <- 0.1*bv - sqrt(max(f2+v2-2*acc,0))*lam.
// ---------------------------------------------------------------------------
__global__ void __launch_bounds__(256, 2)
spectral_hmma(const float* __restrict__ bv, float* __restrict__ out)
{
    extern __shared__ char smem[];
    const uint32_t sbase = smem_u32(smem);

    const int tid = threadIdx.x;
    const int wid = tid >> 5;
    const int lid = tid & 31;
    const int wm = wid & 1;          // M offset wm*64
    const int wn = wid >> 1;         // 0..3 -> N offset wn*32
    const int v0 = blockIdx.x * CTA_N;
    const int m0 = blockIdx.y * CTA_M;

    const int a_row = lid & 15;
    const int a_c16 = (lid >> 4) & 1;
    const int b_row = ((lid >> 4) & 1) * 8 + (lid & 7);
    const int b_c16 = (lid >> 3) & 1;

    float acc[4][4][4];
    #pragma unroll
    for (int mt = 0; mt < 4; mt++)
        #pragma unroll
        for (int nt = 0; nt < 4; nt++)
            #pragma unroll
            for (int e = 0; e < 4; e++) acc[mt][nt][e] = 0.f;

    // fp16 stage loader: 128 rows x 128B each for A and B
    auto load16 = [&](uint32_t stoff, int kc) {
        const uint32_t sb = sbase + stoff;
        #pragma unroll
        for (int i = 0; i < 4; i++) {
            int idx = tid + i * 256;
            int r = idx >> 3, u = idx & 7;
            uint32_t so = (uint32_t)(r * 128 + ((u * 16) ^ ((r & 7) << 4)));
            cpa16(sb + so, g_A16 + (size_t)(m0 + r) * K16 + kc + u * 8);
        }
        #pragma unroll
        for (int i = 0; i < 4; i++) {
            int idx = tid + i * 256;
            int r = idx >> 3, u = idx & 7;
            uint32_t so = (uint32_t)(r * 128 + ((u * 16) ^ ((r & 7) << 4)));
            cpa16(sb + OFF_B + so, g_B16 + (size_t)(v0 + r) * K16 + kc + u * 8);
        }
        CPA_COMMIT();
    };
    // fp8 stage loader: 128 rows x 128B (= 128 fp8 k-lanes)
    auto load8 = [&](uint32_t stoff, int kc8) {
        const uint32_t sb = sbase + stoff;
        #pragma unroll
        for (int i = 0; i < 4; i++) {
            int idx = tid + i * 256;
            int r = idx >> 3, u = idx & 7;
            uint32_t so = (uint32_t)(r * 128 + ((u * 16) ^ ((r & 7) << 4)));
            cpa16(sb + so, g_A8 + (size_t)(m0 + r) * K8 + kc8 + u * 16);
        }
        #pragma unroll
        for (int i = 0; i < 4; i++) {
            int idx = tid + i * 256;
            int r = idx >> 3, u = idx & 7;
            uint32_t so = (uint32_t)(r * 128 + ((u * 16) ^ ((r & 7) << 4)));
            cpa16(sb + OFF_B + so, g_B8 + (size_t)(v0 + r) * K8 + kc8 + u * 16);
        }
        CPA_COMMIT();
    };

    // prologue: chunk0 -> stage0, chunk1 -> stage1
    load16(0, 0);
    load16(STAGE_BYTES, 64);

    #pragma unroll 1
    for (int c = 0; c < NCHUNK; c++) {
        if (c < NCHUNK - 1) { CPA_WAIT1(); } else { CPA_WAIT0(); }
        __syncthreads();

        if (c + 2 < NCHUNK) {
            uint32_t st = (uint32_t)(((c + 2) % 3) * STAGE_BYTES);
            if (c + 2 < 3) load16(st, (c + 2) * 64);
            else           load8(st, (c - 1) * 128);   // c=1 -> kc8 0, c=2 -> 128
        }

        const uint32_t sb = sbase + (uint32_t)((c % 3) * STAGE_BYTES);

        // fragment loads — identical byte addressing for fp16 and fp8 chunks
        #pragma unroll
        for (int ks = 0; ks < 4; ks++) {
            uint32_t ah[4][4], bh[2][4];
            #pragma unroll
            for (int mt = 0; mt < 4; mt++) {
                int R = wm * 64 + mt * 16 + a_row;
                uint32_t off = (uint32_t)(R * 128 + ((ks * 32 + a_c16 * 16) ^ ((R & 7) << 4)));
                LDSM_X4(ah[mt], sb + off);
            }
            #pragma unroll
            for (int ng = 0; ng < 2; ng++) {
                int R = wn * 32 + ng * 16 + b_row;
                uint32_t off = (uint32_t)(R * 128 + ((ks * 32 + b_c16 * 16) ^ ((R & 7) << 4)));
                LDSM_X4(bh[ng], sb + OFF_B + off);
            }
            if (c < 3) {
                #pragma unroll
                for (int mt = 0; mt < 4; mt++)
                    #pragma unroll
                    for (int nt = 0; nt < 4; nt++) {
                        int ng = nt >> 1, sub = nt & 1;
                        MMA16816(acc[mt][nt], ah[mt], bh[ng][sub * 2], bh[ng][sub * 2 + 1]);
                    }
            } else {
                #pragma unroll
                for (int mt = 0; mt < 4; mt++)
                    #pragma unroll
                    for (int nt = 0; nt < 4; nt++) {
                        int ng = nt >> 1, sub = nt & 1;
                        MMA16832F8(acc[mt][nt], ah[mt], bh[ng][sub * 2], bh[ng][sub * 2 + 1]);
                    }
            }
        }

        if (c == 0) {
            // acc = cross (exact quantized distances).  Transform:
            //   acc <- 0.1*bv - sqrt(max(f2+v2-2*acc,0))*lam
            #pragma unroll
            for (int mt = 0; mt < 4; mt++) {
                int r0 = m0 + wm * 64 + mt * 16 + (lid >> 2);
                int r1 = r0 + 8;
                float f2a = g_f2[r0],  lma = g_lamp[r0];
                float f2b = g_f2[r1],  lmb = g_lamp[r1];
                #pragma unroll
                for (int nt = 0; nt < 4; nt++) {
                    int c0 = v0 + wn * 32 + (nt >> 1) * 16 + (nt & 1) * 8 + 2 * (lid & 3);
                    float v2x = g_v2[c0],     bvx = 0.1f * bv[c0];
                    float v2y = g_v2[c0 + 1], bvy = 0.1f * bv[c0 + 1];
                    float* a = acc[mt][nt];
                    a[0] = bvx - sqrtf(fmaxf(f2a + v2x - 2.f * a[0], 0.f)) * lma;
                    a[1] = bvy - sqrtf(fmaxf(f2a + v2y - 2.f * a[1], 0.f)) * lma;
                    a[2] = bvx - sqrtf(fmaxf(f2b + v2x - 2.f * a[2], 0.f)) * lmb;
                    a[3] = bvy - sqrtf(fmaxf(f2b + v2y - 2.f * a[3], 0.f)) * lmb;
                }
            }
        }
    }

    // Writeout
    #pragma unroll
    for (int mt = 0; mt < 4; mt++) {
        size_t r0 = (size_t)(m0 + wm * 64 + mt * 16 + (lid >> 2));
        #pragma unroll
        for (int nt = 0; nt < 4; nt++) {
            int c0 = v0 + wn * 32 + (nt >> 1) * 16 + (nt & 1) * 8 + 2 * (lid & 3);
            float2 lo = make_float2(acc[mt][nt][0], acc[mt][nt][1]);
            float2 hi = make_float2(acc[mt][nt][2], acc[mt][nt][3]);
            *(float2*)(out + r0 * NV + c0)       = lo;
            *(float2*)(out + (r0 + 8) * NV + c0) = hi;
        }
    }
}

// ---------------------------------------------------------------------------
extern "C" void kernel_launch(void* const* d_in, const int* in_sizes, int n_in,
                              void* d_out, int out_size)
{
    const float* wave = (const float*)d_in[0];   // (2,1024,192)
    const float* vf   = (const float*)d_in[1];   // (32000,64)
    const float* vp   = (const float*)d_in[2];   // (32000,64)
    const float* W0   = (const float*)d_in[3];   // (192,256)
    const float* b0   = (const float*)d_in[4];
    const float* W1   = (const float*)d_in[5];   // (256,256)
    const float* b1   = (const float*)d_in[6];
    const float* W2   = (const float*)d_in[7];   // (256,256)
    const float* b2   = (const float*)d_in[8];
    const float* Wv   = (const float*)d_in[9];   // (256,32000)
    const float* bv   = (const float*)d_in[10];  // (32000,)
    const float* rw   = (const float*)d_in[11];  // (3,)
    float* out = (float*)d_out;

    cudaFuncSetAttribute(spectral_hmma,
                         cudaFuncAttributeMaxDynamicSharedMemorySize, SMEM_TOTAL);

    prep_fused<<<NB_PREP, 256>>>(wave, W0, b0, W1, b1, W2, b2, rw, vf, vp, Wv);
    spectral_hmma<<<dim3(NV / CTA_N, NT / CTA_M), 256, SMEM_TOTAL>>>(bv, out);
}